// round 15
// baseline (speedup 1.0000x reference)
#include <cuda_runtime.h>
#include <cstdint>

// ---------------------------------------------------------------------------
// Problem constants
// ---------------------------------------------------------------------------
#define T_STEPS 100
#define B_SZ    32
#define NIN     512
#define N_NEU   2048
#define A_AR    2
#define NC      4096                    // A*N output columns, c = a*2048+n
#define KROWS   4608                    // NIN + NC input rows
#define KCHUNK  144                     // 4608 / 32 k-chunks
#define NKC     32                      // number of k-chunks
#define NBY     8                       // k-splits (4 chunks each)
#define NBG     4                       // batch groups of 8
#define NBLK    (16 * NBG * NBY)        // 512 persistent blocks (single wave)
#define XIS_SZ  (T_STEPS * B_SZ * NIN)  // 1,638,400
#define SS_SZ   (T_STEPS * B_SZ * N_NEU)// 6,553,600 per area
// alpha = float32(exp(-0.1))
#define ALPHA_F 0.9048374180359595731642491f

// ---------------------------------------------------------------------------
// Device-global scratch (static — no allocation anywhere).
// All persistent state is rewritten or zeroed every launch (replay-safe).
// ---------------------------------------------------------------------------
__device__ float         g_W[KROWS * NC];              // fused weights [k][c]
__device__ float         g_V[B_SZ * NC];               // membrane V [b][c]
__device__ float         g_P[NBY * B_SZ * NC];         // partials [by][b][c]
__device__ unsigned char g_mff[T_STEPS * NBG * NIN];   // ff masks per t
__device__ unsigned char g_rec[NBG * NC];              // recurrent masks
__device__ unsigned      g_barc;                       // grid-barrier counter

// ---------------------------------------------------------------------------
// Packed f32x2 helpers (sm_103a) — immune to fast-math contraction
// ---------------------------------------------------------------------------
__device__ __forceinline__ unsigned long long pack2(unsigned lo, unsigned hi) {
    unsigned long long d;
    asm("mov.b64 %0, {%1, %2};" : "=l"(d) : "r"(lo), "r"(hi));
    return d;
}
__device__ __forceinline__ unsigned long long ffma2(unsigned long long a,
                                                    unsigned long long b,
                                                    unsigned long long c) {
    unsigned long long d;
    asm("fma.rn.f32x2 %0, %1, %2, %3;" : "=l"(d) : "l"(a), "l"(b), "l"(c));
    return d;
}
__device__ __forceinline__ unsigned long long fadd2(unsigned long long a,
                                                    unsigned long long b) {
    unsigned long long d;
    asm("add.rn.f32x2 %0, %1, %2;" : "=l"(d) : "l"(a), "l"(b));
    return d;
}
__device__ __forceinline__ float lo32(unsigned long long v) {
    return __uint_as_float((unsigned)v);
}
__device__ __forceinline__ float hi32(unsigned long long v) {
    return __uint_as_float((unsigned)(v >> 32));
}

// ---------------------------------------------------------------------------
// Grid barrier: monotonic counter, no reset races. All NBLK blocks are
// co-resident (single wave enforced by __launch_bounds__(256,4): 64 regs,
// 35KB smem -> 4 blocks/SM, 592 slots >= 512), so spinning is deadlock-free.
// Pattern = cooperative-groups grid.sync(): syncthreads, tid0 fence+arrive+
// spin, syncthreads, fence.
// ---------------------------------------------------------------------------
__device__ __forceinline__ void grid_bar(unsigned target) {
    __syncthreads();
    if (threadIdx.x == 0) {
        __threadfence();
        atomicAdd(&g_barc, 1u);
        while (*(volatile unsigned*)&g_barc < target) __nanosleep(64);
    }
    __syncthreads();
    __threadfence();
}

// ---------------------------------------------------------------------------
// Kernel 1 (prep): three grid-stride jobs, deterministic, atomic-free.
//  A) One thread per (t, bg, i): 8 batch spikes -> Xis floats + g_mff byte.
//  B) Fuse Win [A,NIN,N] + Wrec [S,A,N,N] into g_W[k][c].
//  C) Zero V, g_rec, g_barc (fresh state every launch/replay).
// ---------------------------------------------------------------------------
__global__ void __launch_bounds__(256) mega_prep(const float* __restrict__ rates,
                                                 const float* __restrict__ noise,
                                                 const float* __restrict__ Win,
                                                 const float* __restrict__ Wrec,
                                                 float* __restrict__ out) {
    const int gsz  = gridDim.x * blockDim.x;
    const int tid0 = blockIdx.x * blockDim.x + threadIdx.x;

    if (tid0 == 0) g_barc = 0u;

    // ---- Job A: spikes + ff mask bytes ----
    const int na = T_STEPS * NBG * NIN;
    for (int idx = tid0; idx < na; idx += gsz) {
        int t  = idx / (NBG * NIN);
        int r  = idx - t * (NBG * NIN);
        int bg = r >> 9;               // / NIN
        int i  = r & (NIN - 1);
        unsigned m = 0;
#pragma unroll
        for (int b8 = 0; b8 < 8; b8++) {
            int e = (t * B_SZ + bg * 8 + b8) * NIN + i;
            float rt = rates[e];
            float nz = noise[e];
            bool sp = nz < __fmul_rn(rt, 1e-3f);
            out[e] = sp ? 1.0f : 0.0f;
            m |= (sp ? 1u : 0u) << b8;
        }
        g_mff[idx] = (unsigned char)m;
    }

    // ---- Job B: pack W ----
    const int total4 = KROWS * NC / 4;
    for (int idx = tid0; idx < total4; idx += gsz) {
        int e = idx << 2;
        int k = e >> 12;              // / 4096
        int c = e & (NC - 1);
        int a = c >> 11;
        int n = c & (N_NEU - 1);
        float4 v;
        if (k < NIN) {
            v = *(const float4*)&Win[(a * NIN + k) * N_NEU + n];
        } else {
            int kr = k - NIN;
            int s  = kr >> 11;
            int m  = kr & (N_NEU - 1);
            v = *(const float4*)&Wrec[(((s * A_AR + a) * N_NEU) + m) * (size_t)N_NEU + n];
        }
        *(float4*)&g_W[e] = v;
    }

    // ---- Job C: zero V + recurrent masks ----
    for (int idx = tid0; idx < B_SZ * NC; idx += gsz) g_V[idx] = 0.0f;
    for (int idx = tid0; idx < NBG * NC / 4; idx += gsz)
        ((unsigned*)g_rec)[idx] = 0u;
}

// ---------------------------------------------------------------------------
// Persistent simulation kernel: all 100 steps in one launch.
// Per step: (gemm phases identical to R14) -> grid barrier -> (update,
// identical arithmetic to R14, distributed 32 idx per block) -> grid barrier.
// Cross-step cross-SM data (g_rec in phase-1, g_P in update) is read via
// __ldcg to bypass L1 (L1D is only flushed at launch boundaries on sm_103a).
// ---------------------------------------------------------------------------
struct SmemP1 {
    unsigned list[4][KCHUNK];       // W byte offsets (k * NC * 4), ascending
    float    spk[4][KCHUNK][8];     // expanded spike floats
    int      cnt[4];
};
union SmemU {
    SmemP1 p1;
    unsigned long long sbuf[8][32][17];   // reduce buffer (16 u64 + pad)
};

__device__ __forceinline__ void fma_row(unsigned long long acc[4][4],
                                        float4 wv, const float* __restrict__ sp) {
    float4 sA = *(const float4*)sp;
    float4 sB = *(const float4*)(sp + 4);
    unsigned long long s2[4];
    s2[0] = pack2(__float_as_uint(sA.x), __float_as_uint(sA.y));
    s2[1] = pack2(__float_as_uint(sA.z), __float_as_uint(sA.w));
    s2[2] = pack2(__float_as_uint(sB.x), __float_as_uint(sB.y));
    s2[3] = pack2(__float_as_uint(sB.z), __float_as_uint(sB.w));
    unsigned wb[4] = {__float_as_uint(wv.x), __float_as_uint(wv.y),
                      __float_as_uint(wv.z), __float_as_uint(wv.w)};
#pragma unroll
    for (int c = 0; c < 4; c++) {
        unsigned long long w2 = pack2(wb[c], wb[c]);
#pragma unroll
        for (int j = 0; j < 4; j++)
            acc[c][j] = ffma2(w2, s2[j], acc[c][j]);
    }
}

__global__ void __launch_bounds__(256, 4) sim_all(float* __restrict__ out) {
    __shared__ SmemU sm;

    const int tid  = threadIdx.x;
    const int w    = tid >> 5;
    const int lane = tid & 31;
    const int cw   = w & 1;          // column half within block
    const int ksub = w >> 1;         // 0..3
    const int ct   = blockIdx.x;     // 0..15
    const int bg   = blockIdx.y;     // batch group (8 batches)
    const int by   = blockIdx.z;     // partial index
    const int bid  = ct + 16 * bg + 64 * by;   // 0..511
    const int c0   = ct * 256 + cw * 128 + lane * 4;

    unsigned barno = 0;

    for (int t = 0; t < T_STEPS; t++) {
        // ---- Phase 1: warps 0..3 compact chunk (by*4 + w) for this bg ----
        if (w < 4) {
            const int kc = by * 4 + w;
            const int k0 = kc * KCHUNK;
            const unsigned char* __restrict__ mff_t = &g_mff[(t * NBG + bg) * NIN];
            const unsigned char* __restrict__ recb  = &g_rec[bg * NC];
            int total = 0;
#pragma unroll
            for (int it = 0; it < 5; it++) {
                int r = it * 32 + lane;
                int k = k0 + r;
                unsigned msk = 0u;
                if (r < KCHUNK)
                    msk = (k < NIN) ? (unsigned)mff_t[k]
                                    : (unsigned)__ldcg(&recb[k - NIN]);
                bool act = msk != 0u;
                unsigned bal = __ballot_sync(0xFFFFFFFFu, act);
                if (act) {
                    int pos = total + __popc(bal & ((1u << lane) - 1u));
                    sm.p1.list[w][pos] = (unsigned)k * (NC * 4);
#pragma unroll
                    for (int b = 0; b < 8; b++)
                        sm.p1.spk[w][pos][b] = (msk >> b) & 1u ? 1.0f : 0.0f;
                }
                total += __popc(bal);
            }
            if (lane == 0) sm.p1.cnt[w] = total;
        }
        __syncthreads();

        // ---- Phase 2: sparse FMA loop, 2-row batched W prefetch ----
        const int n = sm.p1.cnt[ksub];
        const unsigned* __restrict__ lst = sm.p1.list[ksub];
        const float*    __restrict__ spk = &sm.p1.spk[ksub][0][0];
        const char* __restrict__ wbase = (const char*)g_W + (unsigned)c0 * 4u;

        unsigned long long acc[4][4];
#pragma unroll
        for (int c = 0; c < 4; c++)
#pragma unroll
            for (int j = 0; j < 4; j++) acc[c][j] = 0ull;

        int i = 0;
        for (; i + 2 <= n; i += 2) {
            uint2 off = *(const uint2*)&lst[i];           // one LDS.64
            float4 wv0 = *(const float4*)(wbase + off.x); // 2 indep LDG.128
            float4 wv1 = *(const float4*)(wbase + off.y);
            fma_row(acc, wv0, &spk[(i + 0) * 8]);
            fma_row(acc, wv1, &spk[(i + 1) * 8]);
        }
        for (; i < n; i++) {
            unsigned off = lst[i];
            float4 wv = *(const float4*)(wbase + off);
            fma_row(acc, wv, &spk[i * 8]);
        }

        __syncthreads();   // phase-1 data consumed; reuse shared as sbuf

#pragma unroll
        for (int c = 0; c < 4; c++)
#pragma unroll
            for (int j = 0; j < 4; j++) sm.sbuf[w][lane][c * 4 + j] = acc[c][j];
        __syncthreads();

        if (ksub == 0) {
#pragma unroll
            for (int ks = 1; ks < 4; ks++) {
#pragma unroll
                for (int c = 0; c < 4; c++)
#pragma unroll
                    for (int j = 0; j < 4; j++)
                        acc[c][j] = fadd2(acc[c][j],
                                          sm.sbuf[ks * 2 + cw][lane][c * 4 + j]);
            }
            // transposed, coalesced stores: g_P[by][b][c0..c0+3]
#pragma unroll
            for (int j = 0; j < 4; j++) {
                int b = bg * 8 + 2 * j;
                float4 lo4 = make_float4(lo32(acc[0][j]), lo32(acc[1][j]),
                                         lo32(acc[2][j]), lo32(acc[3][j]));
                float4 hi4 = make_float4(hi32(acc[0][j]), hi32(acc[1][j]),
                                         hi32(acc[2][j]), hi32(acc[3][j]));
                *(float4*)&g_P[(unsigned)((by * B_SZ + b)     * NC) + c0] = lo4;
                *(float4*)&g_P[(unsigned)((by * B_SZ + b + 1) * NC) + c0] = hi4;
            }
        }

        grid_bar(++barno * NBLK);   // all partials of step t visible

        // ---- Update phase: 32 idx per block, identical arithmetic to R14 ----
        if (tid < 32) {
            int idx = bid * 32 + tid;          // 0 .. 16383
            int ubg = idx >> 12;
            int c   = idx & (NC - 1);
            int a   = c >> 11;
            int nn  = c & (N_NEU - 1);

            unsigned oldm = g_rec[ubg * NC + c];   // own write from t-1 (local)
            unsigned newm = 0;

#pragma unroll
            for (int b8 = 0; b8 < 8; b8++) {
                int b = ubg * 8 + b8;
                float I = __ldcg(&g_P[(0 * B_SZ + b) * NC + c]);
#pragma unroll
                for (int byi = 1; byi < NBY; byi++)
                    I = __fadd_rn(I, __ldcg(&g_P[(byi * B_SZ + b) * NC + c]));

                float xd   = (oldm >> b8) & 1u ? 1.0f : 0.0f;
                float Vold = g_V[b * NC + c];
                float Vnew = __fadd_rn(__fmul_rn(__fmul_rn(ALPHA_F, Vold),
                                                 __fsub_rn(1.0f, xd)), I);
                unsigned s = Vnew >= 1.0f ? 1u : 0u;
                g_V[b * NC + c] = Vnew;
                newm |= s << b8;
                out[XIS_SZ + a * SS_SZ + t * (B_SZ * N_NEU) + b * N_NEU + nn] =
                    s ? 1.0f : 0.0f;
            }

            g_rec[ubg * NC + c] = (unsigned char)newm;
        }

        grid_bar(++barno * NBLK);   // all rec masks of step t visible
    }
}

// ---------------------------------------------------------------------------
// Launch: 1 prep kernel + 1 persistent kernel. Graph-capturable (plain
// launches only), replay-deterministic (barrier counter re-zeroed in prep).
// ---------------------------------------------------------------------------
extern "C" void kernel_launch(void* const* d_in, const int* in_sizes, int n_in,
                              void* d_out, int out_size) {
    const float* rates = (const float*)d_in[0];
    const float* noise = (const float*)d_in[1];
    const float* Win   = (const float*)d_in[2];
    const float* Wrec  = (const float*)d_in[3];
    float* out = (float*)d_out;

    mega_prep<<<2048, 256>>>(rates, noise, Win, Wrec, out);
    sim_all<<<dim3(16, NBG, NBY), 256>>>(out);
}